// round 8
// baseline (speedup 1.0000x reference)
#include <cuda_runtime.h>
#include <math.h>

// DiceLoss: logits [8,19,512,512] f32, targets [8,512,512] int32 (harness downcasts i64)
#define NC 19
#define HW (512LL * 512LL)
#define PIX_PER_CTA 2048LL   // 16 iters * 128 threads; 8KB-aligned chunks; grid=1024 <= 1 wave

// Scratch: probs_sum[0..18], inter[19..37], cnt[38..56]
__device__ float g_acc[3 * NC];
__device__ unsigned int g_done;

__global__ __launch_bounds__(128, 7) void dice_fused_kernel(
    const float* __restrict__ logits,
    const int* __restrict__ targets,
    long long npix,
    float* __restrict__ out)
{
    // Per-thread slots: word index c*128+tid -> bank tid%32, conflict-free, NO atomics.
    __shared__ float s_int[NC * 128];
    __shared__ int   s_cnt[NC * 128];
    __shared__ float s_psum[NC];
    __shared__ int   s_last;

    const int tid = threadIdx.x;
#pragma unroll
    for (int i = tid; i < NC * 128; i += 128) { s_int[i] = 0.0f; s_cnt[i] = 0; }
    if (tid < NC) s_psum[tid] = 0.0f;
    __syncthreads();

    float acc[NC];
#pragma unroll
    for (int c = 0; c < NC; c++) acc[c] = 0.0f;

    const long long start = (long long)blockIdx.x * PIX_PER_CTA;
    long long end = start + PIX_PER_CTA;
    if (end > npix) end = npix;

    for (long long p = start + tid; p < end; p += 128) {
        const int t = targets[p];
        const long long b  = p >> 18;            // p / HW
        const long long hw = p & (HW - 1);       // p % HW
        const float* __restrict__ base = logits + b * (long long)NC * HW + hw;

        // Stage all 19 channel logits (independent loads -> MLP=19/thread).
        float e[NC];
#pragma unroll
        for (int c = 0; c < NC; c++) e[c] = base[(long long)c * HW];

        float s = 0.0f;
#pragma unroll
        for (int c = 0; c < NC; c++) { e[c] = __expf(e[c]); s += e[c]; }

        const bool valid = (unsigned)t < NC;
        const float inv = valid ? __frcp_rn(s) : 0.0f;   // masked probs everywhere

        float gathered = 0.0f;
#pragma unroll
        for (int c = 0; c < NC; c++) {
            const float pr = e[c] * inv;
            acc[c] += pr;
            if (c == t) gathered = pr;
        }
        if (valid) {
            const int slot = t * 128 + tid;      // conflict-free per-lane slot
            s_int[slot] += gathered;
            s_cnt[slot] += 1;
        }
    }

    // psum: warp-reduce register accumulators, one shared atomic per warp per class
    // (epilogue-only atomics: 19*4 per CTA, negligible).
#pragma unroll
    for (int c = 0; c < NC; c++) {
        float v = acc[c];
#pragma unroll
        for (int o = 16; o > 0; o >>= 1) v += __shfl_xor_sync(0xffffffffu, v, o);
        if ((tid & 31) == 0) atomicAdd(&s_psum[c], v);
    }
    __syncthreads();

    if (tid < NC) atomicAdd(&g_acc[tid], s_psum[tid]);

    // inter / cnt: reduce the 19x128 slot arrays. Warp w handles classes w, w+4, ...
    {
        const int warp = tid >> 5;
        const int lane = tid & 31;
        for (int c = warp; c < NC; c += 4) {
            const int o0 = c * 128 + lane;
            float vi = s_int[o0] + s_int[o0 + 32] + s_int[o0 + 64] + s_int[o0 + 96];
            float vc = (float)(s_cnt[o0] + s_cnt[o0 + 32] + s_cnt[o0 + 64] + s_cnt[o0 + 96]);
#pragma unroll
            for (int o = 16; o > 0; o >>= 1) {
                vi += __shfl_xor_sync(0xffffffffu, vi, o);
                vc += __shfl_xor_sync(0xffffffffu, vc, o);
            }
            if (lane == 0) {
                atomicAdd(&g_acc[NC + c], vi);
                atomicAdd(&g_acc[2 * NC + c], vc);
            }
        }
    }

    // Last-block-done: finalize + reset scratch for the next (graph-replayed) call.
    __threadfence();
    if (tid == 0) {
        unsigned prev = atomicAdd(&g_done, 1u);
        s_last = (prev == gridDim.x - 1) ? 1 : 0;
    }
    __syncthreads();

    if (s_last) {
        if (tid < 32) {
            float contrib = 0.0f;
            float cntv = 0.0f;
            if (tid < NC) {
                // atomic reads bypass potentially-stale L1
                const float psum  = atomicAdd(&g_acc[tid], 0.0f);
                const float inter = atomicAdd(&g_acc[NC + tid], 0.0f);
                const float cnt   = atomicAdd(&g_acc[2 * NC + tid], 0.0f);
                contrib = 1.0f - (2.0f * inter + 1.0f) / (psum + cnt + 1.0f);
                cntv = cnt;
            }
#pragma unroll
            for (int o = 16; o > 0; o >>= 1) {
                contrib += __shfl_xor_sync(0xffffffffu, contrib, o);
                cntv    += __shfl_xor_sync(0xffffffffu, cntv, o);
            }
            if (tid == 0)
                out[0] = (cntv > 0.0f) ? (contrib / (float)NC) : 0.0f;
        }
        __syncthreads();
        if (tid < 3 * NC) g_acc[tid] = 0.0f;
        if (tid == 0) g_done = 0u;
    }
}

extern "C" void kernel_launch(void* const* d_in, const int* in_sizes, int n_in,
                              void* d_out, int out_size) {
    const float* logits  = (const float*)d_in[0];
    const int*   targets = (const int*)d_in[1];
    float* out = (float*)d_out;

    const long long npix = (long long)in_sizes[1];   // B*H*W = 2,097,152
    const int grid = (int)((npix + PIX_PER_CTA - 1) / PIX_PER_CTA);   // 1024

    dice_fused_kernel<<<grid, 128>>>(logits, targets, npix, out);
}